// round 1
// baseline (speedup 1.0000x reference)
#include <cuda_runtime.h>
#include <cstdint>

#define N_NODES 100000
#define N_EDGES 1000000
#define F_IN    128
#define H_OUT   64
#define BN_EPS  1e-3f

// ---------------- device scratch (no allocs allowed) ----------------
__device__ float g_h[(size_t)N_NODES * H_OUT];   // BN-scaled hidden features, 25.6 MB
__device__ int   g_deg[N_NODES];
__device__ float g_isd[N_NODES];                 // deg^-0.5
__device__ float g_t[H_OUT];                     // BN offset: beta - mean*s

// ---------------- small prep kernels ----------------
__global__ void zero_deg_kernel() {
    int i = blockIdx.x * blockDim.x + threadIdx.x;
    if (i < N_NODES) g_deg[i] = 0;
}

__global__ void count_deg_kernel(const int2* __restrict__ ei) {
    int e = blockIdx.x * blockDim.x + threadIdx.x;
    if (e < N_EDGES) atomicAdd(&g_deg[ei[e].x], 1);
}

__global__ void isd_kernel() {
    int i = blockIdx.x * blockDim.x + threadIdx.x;
    if (i < N_NODES) {
        float d = (float)g_deg[i];
        g_isd[i] = (d > 0.f) ? rsqrtf(d) : 0.f;
    }
}

__global__ void bn_prep_kernel(const float* __restrict__ gamma,
                               const float* __restrict__ beta,
                               const float* __restrict__ mean,
                               const float* __restrict__ var) {
    int j = threadIdx.x;
    if (j < H_OUT) {
        float s = gamma[j] * rsqrtf(var[j] + BN_EPS);
        g_t[j] = beta[j] - mean[j] * s;
    }
}

// ---------------- GEMM: g_h = (X @ W + b) * s  (s = BN scale folded in) ----------------
// Block: 256 threads, 128 nodes. Thread (g = t>>3, cg = t&7) computes a 4x8 register
// tile: nodes 4g..4g+3, cols {4cg..4cg+3} U {32+4cg..32+4cg+3}.
#define GEMM_NODES 128
#define XS_PITCH   129
#define GEMM_SMEM  (F_IN * H_OUT * 4 + GEMM_NODES * XS_PITCH * 4)

__global__ __launch_bounds__(256, 2) void gemm_kernel(
    const float* __restrict__ X, const float* __restrict__ W,
    const float* __restrict__ bias,
    const float* __restrict__ gamma, const float* __restrict__ var)
{
    extern __shared__ float smem[];
    float* Ws = smem;                         // [128][64], BN-scaled W
    float* Xs = smem + F_IN * H_OUT;          // [128][129]

    int t = threadIdx.x;
    int node0 = blockIdx.x * GEMM_NODES;

    // Load W, scaling each column by s_j
    for (int i = t; i < F_IN * H_OUT; i += 256) {
        int j = i & (H_OUT - 1);
        float s = gamma[j] * rsqrtf(var[j] + BN_EPS);
        Ws[i] = W[i] * s;
    }
    // Load X tile (128 rows x 128 cols) via float4, coalesced
    for (int i = t; i < GEMM_NODES * (F_IN / 4); i += 256) {
        int r  = i >> 5;          // row 0..127
        int c4 = i & 31;          // float4 index 0..31
        int n = node0 + r;
        float4 v = make_float4(0.f, 0.f, 0.f, 0.f);
        if (n < N_NODES) v = *(const float4*)&X[(size_t)n * F_IN + c4 * 4];
        float* dst = &Xs[r * XS_PITCH + c4 * 4];
        dst[0] = v.x; dst[1] = v.y; dst[2] = v.z; dst[3] = v.w;
    }
    __syncthreads();

    int g  = t >> 3;   // 0..31
    int cg = t & 7;    // 0..7
    int nb = g * 4;
    int ca = cg * 4;         // first col block
    int cb = 32 + cg * 4;    // second col block

    float acc[4][8];
    #pragma unroll
    for (int i = 0; i < 4; i++)
        #pragma unroll
        for (int j = 0; j < 8; j++) acc[i][j] = 0.f;

    #pragma unroll 8
    for (int k = 0; k < F_IN; k++) {
        float x0 = Xs[(nb + 0) * XS_PITCH + k];
        float x1 = Xs[(nb + 1) * XS_PITCH + k];
        float x2 = Xs[(nb + 2) * XS_PITCH + k];
        float x3 = Xs[(nb + 3) * XS_PITCH + k];
        float4 wa = *(const float4*)&Ws[k * H_OUT + ca];
        float4 wb = *(const float4*)&Ws[k * H_OUT + cb];
        acc[0][0] += x0 * wa.x; acc[0][1] += x0 * wa.y; acc[0][2] += x0 * wa.z; acc[0][3] += x0 * wa.w;
        acc[0][4] += x0 * wb.x; acc[0][5] += x0 * wb.y; acc[0][6] += x0 * wb.z; acc[0][7] += x0 * wb.w;
        acc[1][0] += x1 * wa.x; acc[1][1] += x1 * wa.y; acc[1][2] += x1 * wa.z; acc[1][3] += x1 * wa.w;
        acc[1][4] += x1 * wb.x; acc[1][5] += x1 * wb.y; acc[1][6] += x1 * wb.z; acc[1][7] += x1 * wb.w;
        acc[2][0] += x2 * wa.x; acc[2][1] += x2 * wa.y; acc[2][2] += x2 * wa.z; acc[2][3] += x2 * wa.w;
        acc[2][4] += x2 * wb.x; acc[2][5] += x2 * wb.y; acc[2][6] += x2 * wb.z; acc[2][7] += x2 * wb.w;
        acc[3][0] += x3 * wa.x; acc[3][1] += x3 * wa.y; acc[3][2] += x3 * wa.z; acc[3][3] += x3 * wa.w;
        acc[3][4] += x3 * wb.x; acc[3][5] += x3 * wb.y; acc[3][6] += x3 * wb.z; acc[3][7] += x3 * wb.w;
    }

    // bias (scaled) for this thread's 8 columns
    float bs[8];
    #pragma unroll
    for (int j = 0; j < 4; j++) {
        int c1 = ca + j, c2 = cb + j;
        bs[j]     = bias[c1] * (gamma[c1] * rsqrtf(var[c1] + BN_EPS));
        bs[4 + j] = bias[c2] * (gamma[c2] * rsqrtf(var[c2] + BN_EPS));
    }

    #pragma unroll
    for (int i = 0; i < 4; i++) {
        int n = node0 + nb + i;
        if (n < N_NODES) {
            float4 oa = make_float4(acc[i][0] + bs[0], acc[i][1] + bs[1],
                                    acc[i][2] + bs[2], acc[i][3] + bs[3]);
            float4 ob = make_float4(acc[i][4] + bs[4], acc[i][5] + bs[5],
                                    acc[i][6] + bs[6], acc[i][7] + bs[7]);
            *(float4*)&g_h[(size_t)n * H_OUT + ca] = oa;
            *(float4*)&g_h[(size_t)n * H_OUT + cb] = ob;
        }
    }
}

// ---------------- out init: out = t + 0.5 * (deg^2/max(deg,1)) * h2 ----------------
__global__ void init_out_kernel(float* __restrict__ out) {
    int idx = blockIdx.x * blockDim.x + threadIdx.x;
    int i = idx >> 4;        // node
    int q = idx & 15;        // float4 chunk within 64-col row
    if (i >= N_NODES) return;
    float d  = (float)g_deg[i];
    float de = (d > 0.f) ? (d * d / fmaxf(d, 1.f)) : 0.f;
    float c  = 0.5f * de;
    float4 tt = *(const float4*)&g_t[q * 4];
    float4 h  = *(const float4*)&g_h[(size_t)i * H_OUT + q * 4];
    float4 o  = make_float4(tt.x + c * h.x, tt.y + c * h.y,
                            tt.z + c * h.z, tt.w + c * h.w);
    *(float4*)&out[(size_t)i * H_OUT + q * 4] = o;
}

// ---------------- edge scatter: out[src] += 0.5*isd[s]*isd[d]*h2[dst] ----------------
// One thread per (edge, float4-chunk): 16 chunks per edge. Vector red.v4 atomics.
__global__ void edge_kernel(const int2* __restrict__ ei, float* __restrict__ out) {
    int idx = blockIdx.x * blockDim.x + threadIdx.x;
    int e = idx >> 4;
    int q = idx & 15;
    if (e >= N_EDGES) return;
    int2 p = __ldg(&ei[e]);
    int s = p.x, d = p.y;
    float scale = 0.5f * g_isd[s] * g_isd[d];
    float4 v = *(const float4*)&g_h[(size_t)d * H_OUT + q * 4];
    float* dst = &out[(size_t)s * H_OUT + q * 4];
    asm volatile("red.global.add.v4.f32 [%0], {%1, %2, %3, %4};"
                 :: "l"(dst),
                    "f"(v.x * scale), "f"(v.y * scale),
                    "f"(v.z * scale), "f"(v.w * scale)
                 : "memory");
}

// ---------------- launch ----------------
extern "C" void kernel_launch(void* const* d_in, const int* in_sizes, int n_in,
                              void* d_out, int out_size) {
    const float* X     = (const float*)d_in[0];
    const float* W     = (const float*)d_in[1];
    const float* bias  = (const float*)d_in[2];
    const float* gamma = (const float*)d_in[3];
    const float* beta  = (const float*)d_in[4];
    const float* mean  = (const float*)d_in[5];
    const float* var   = (const float*)d_in[6];
    const int2*  ei    = (const int2*)d_in[7];
    float* out = (float*)d_out;

    zero_deg_kernel<<<(N_NODES + 255) / 256, 256>>>();
    count_deg_kernel<<<(N_EDGES + 255) / 256, 256>>>(ei);
    isd_kernel<<<(N_NODES + 255) / 256, 256>>>();
    bn_prep_kernel<<<1, 64>>>(gamma, beta, mean, var);

    cudaFuncSetAttribute(gemm_kernel, cudaFuncAttributeMaxDynamicSharedMemorySize, GEMM_SMEM);
    gemm_kernel<<<(N_NODES + GEMM_NODES - 1) / GEMM_NODES, 256, GEMM_SMEM>>>(X, W, bias, gamma, var);

    init_out_kernel<<<(N_NODES * 16 + 255) / 256, 256>>>(out);
    edge_kernel<<<(N_EDGES * 16 + 255) / 256, 256>>>(ei, out);
}

// round 2
// speedup vs baseline: 1.0567x; 1.0567x over previous
#include <cuda_runtime.h>
#include <cstdint>

#define N_NODES 100000
#define N_EDGES 1000000
#define F_IN    128
#define H_OUT   64
#define BN_EPS  1e-3f

#define SCAN_NODES_PER_BLOCK 1024
#define SCAN_THREADS 256
#define N_SCAN_BLOCKS ((N_NODES + SCAN_NODES_PER_BLOCK - 1) / SCAN_NODES_PER_BLOCK)  // 98

// ---------------- device scratch (no allocs allowed) ----------------
__device__ float g_h[(size_t)N_NODES * H_OUT];   // BN-scaled hidden features, 25.6 MB
__device__ int   g_deg[N_NODES];
__device__ float g_isd[N_NODES];                 // deg^-0.5
__device__ int   g_rowstart[N_NODES];            // CSR row offsets
__device__ int   g_cursor[N_NODES];              // scatter cursors
__device__ int   g_edst[N_EDGES];                // CSR column (dst) ids
__device__ int   g_bsum[128];                    // per-block degree sums
__device__ int   g_boff[128];                    // exclusive-scanned block offsets

// ---------------- prep ----------------
__global__ void zero_deg_kernel() {
    int i = blockIdx.x * blockDim.x + threadIdx.x;
    if (i < N_NODES) g_deg[i] = 0;
}

__global__ void count_deg_kernel(const int2* __restrict__ ei) {
    int e = blockIdx.x * blockDim.x + threadIdx.x;
    if (e < N_EDGES) atomicAdd(&g_deg[ei[e].x], 1);
}

// scan stage A: per-block degree sums (1024 nodes / block, 256 threads)
__global__ void scanA_kernel() {
    __shared__ int wsum[8];
    int b = blockIdx.x, t = threadIdx.x;
    int base = b * SCAN_NODES_PER_BLOCK + t * 4;
    int s = 0;
    #pragma unroll
    for (int j = 0; j < 4; j++)
        if (base + j < N_NODES) s += g_deg[base + j];
    #pragma unroll
    for (int o = 16; o > 0; o >>= 1) s += __shfl_down_sync(0xffffffffu, s, o);
    if ((t & 31) == 0) wsum[t >> 5] = s;
    __syncthreads();
    if (t == 0) {
        int tot = 0;
        #pragma unroll
        for (int w = 0; w < 8; w++) tot += wsum[w];
        g_bsum[b] = tot;
    }
}

// scan stage B: exclusive scan of <=128 block sums (single block)
__global__ void scanB_kernel() {
    __shared__ int sm[128];
    int t = threadIdx.x;
    int v = (t < N_SCAN_BLOCKS) ? g_bsum[t] : 0;
    sm[t] = v;
    __syncthreads();
    #pragma unroll
    for (int off = 1; off < 128; off <<= 1) {
        int u = (t >= off) ? sm[t - off] : 0;
        __syncthreads();
        sm[t] += u;
        __syncthreads();
    }
    if (t < N_SCAN_BLOCKS) g_boff[t] = sm[t] - v;
}

// scan stage C: per-node row starts + cursors + isd
__global__ void scanC_kernel() {
    __shared__ int sm[SCAN_THREADS];
    int b = blockIdx.x, t = threadIdx.x;
    int base = b * SCAN_NODES_PER_BLOCK + t * 4;
    int d[4];
    int s = 0;
    #pragma unroll
    for (int j = 0; j < 4; j++) {
        d[j] = (base + j < N_NODES) ? g_deg[base + j] : 0;
        s += d[j];
    }
    sm[t] = s;
    __syncthreads();
    #pragma unroll
    for (int off = 1; off < SCAN_THREADS; off <<= 1) {
        int u = (t >= off) ? sm[t - off] : 0;
        __syncthreads();
        sm[t] += u;
        __syncthreads();
    }
    int row = g_boff[b] + (sm[t] - s);
    #pragma unroll
    for (int j = 0; j < 4; j++) {
        int i = base + j;
        if (i < N_NODES) {
            g_rowstart[i] = row;
            g_cursor[i]   = row;
            float dd = (float)d[j];
            g_isd[i] = (dd > 0.f) ? rsqrtf(dd) : 0.f;
            row += d[j];
        }
    }
}

// bucket scatter: edges -> CSR by src
__global__ void scatter_kernel(const int2* __restrict__ ei) {
    int e = blockIdx.x * blockDim.x + threadIdx.x;
    if (e < N_EDGES) {
        int2 p = __ldg(&ei[e]);
        int pos = atomicAdd(&g_cursor[p.x], 1);
        g_edst[pos] = p.y;
    }
}

// ---------------- GEMM: g_h = (X @ W + b) * s  (BN scale folded) ----------------
#define GEMM_NODES 128
#define XS_PITCH   129
#define GEMM_SMEM  (F_IN * H_OUT * 4 + GEMM_NODES * XS_PITCH * 4)

__global__ __launch_bounds__(256, 2) void gemm_kernel(
    const float* __restrict__ X, const float* __restrict__ W,
    const float* __restrict__ bias,
    const float* __restrict__ gamma, const float* __restrict__ var)
{
    extern __shared__ float smem[];
    float* Ws = smem;                         // [128][64], BN-scaled W
    float* Xs = smem + F_IN * H_OUT;          // [128][129]

    int t = threadIdx.x;
    int node0 = blockIdx.x * GEMM_NODES;

    for (int i = t; i < F_IN * H_OUT; i += 256) {
        int j = i & (H_OUT - 1);
        float s = gamma[j] * rsqrtf(var[j] + BN_EPS);
        Ws[i] = W[i] * s;
    }
    for (int i = t; i < GEMM_NODES * (F_IN / 4); i += 256) {
        int r  = i >> 5;
        int c4 = i & 31;
        int n = node0 + r;
        float4 v = make_float4(0.f, 0.f, 0.f, 0.f);
        if (n < N_NODES) v = *(const float4*)&X[(size_t)n * F_IN + c4 * 4];
        float* dst = &Xs[r * XS_PITCH + c4 * 4];
        dst[0] = v.x; dst[1] = v.y; dst[2] = v.z; dst[3] = v.w;
    }
    __syncthreads();

    int g  = t >> 3;
    int cg = t & 7;
    int nb = g * 4;
    int ca = cg * 4;
    int cb = 32 + cg * 4;

    float acc[4][8];
    #pragma unroll
    for (int i = 0; i < 4; i++)
        #pragma unroll
        for (int j = 0; j < 8; j++) acc[i][j] = 0.f;

    #pragma unroll 8
    for (int k = 0; k < F_IN; k++) {
        float x0 = Xs[(nb + 0) * XS_PITCH + k];
        float x1 = Xs[(nb + 1) * XS_PITCH + k];
        float x2 = Xs[(nb + 2) * XS_PITCH + k];
        float x3 = Xs[(nb + 3) * XS_PITCH + k];
        float4 wa = *(const float4*)&Ws[k * H_OUT + ca];
        float4 wb = *(const float4*)&Ws[k * H_OUT + cb];
        acc[0][0] += x0 * wa.x; acc[0][1] += x0 * wa.y; acc[0][2] += x0 * wa.z; acc[0][3] += x0 * wa.w;
        acc[0][4] += x0 * wb.x; acc[0][5] += x0 * wb.y; acc[0][6] += x0 * wb.z; acc[0][7] += x0 * wb.w;
        acc[1][0] += x1 * wa.x; acc[1][1] += x1 * wa.y; acc[1][2] += x1 * wa.z; acc[1][3] += x1 * wa.w;
        acc[1][4] += x1 * wb.x; acc[1][5] += x1 * wb.y; acc[1][6] += x1 * wb.z; acc[1][7] += x1 * wb.w;
        acc[2][0] += x2 * wa.x; acc[2][1] += x2 * wa.y; acc[2][2] += x2 * wa.z; acc[2][3] += x2 * wa.w;
        acc[2][4] += x2 * wb.x; acc[2][5] += x2 * wb.y; acc[2][6] += x2 * wb.z; acc[2][7] += x2 * wb.w;
        acc[3][0] += x3 * wa.x; acc[3][1] += x3 * wa.y; acc[3][2] += x3 * wa.z; acc[3][3] += x3 * wa.w;
        acc[3][4] += x3 * wb.x; acc[3][5] += x3 * wb.y; acc[3][6] += x3 * wb.z; acc[3][7] += x3 * wb.w;
    }

    float bs[8];
    #pragma unroll
    for (int j = 0; j < 4; j++) {
        int c1 = ca + j, c2 = cb + j;
        bs[j]     = bias[c1] * (gamma[c1] * rsqrtf(var[c1] + BN_EPS));
        bs[4 + j] = bias[c2] * (gamma[c2] * rsqrtf(var[c2] + BN_EPS));
    }

    #pragma unroll
    for (int i = 0; i < 4; i++) {
        int n = node0 + nb + i;
        if (n < N_NODES) {
            float4 oa = make_float4(acc[i][0] + bs[0], acc[i][1] + bs[1],
                                    acc[i][2] + bs[2], acc[i][3] + bs[3]);
            float4 ob = make_float4(acc[i][4] + bs[4], acc[i][5] + bs[5],
                                    acc[i][6] + bs[6], acc[i][7] + bs[7]);
            *(float4*)&g_h[(size_t)n * H_OUT + ca] = oa;
            *(float4*)&g_h[(size_t)n * H_OUT + cb] = ob;
        }
    }
}

// ---------------- fused gather: warp per node ----------------
// out[i] = t + 0.5*deg[i]*h[i] + 0.5*isd[i]*sum_{d in adj(i)} isd[d]*h[d]
__global__ __launch_bounds__(256) void gather_kernel(
    const float* __restrict__ gamma, const float* __restrict__ beta,
    const float* __restrict__ mean,  const float* __restrict__ var,
    float* __restrict__ out)
{
    int w    = (blockIdx.x * blockDim.x + threadIdx.x) >> 5;
    int lane = threadIdx.x & 31;
    if (w >= N_NODES) return;

    int start = g_rowstart[w];
    int deg   = g_deg[w];
    int end   = start + deg;
    int c     = lane * 2;

    float accx = 0.f, accy = 0.f;

    for (int base = start; base < end; base += 32) {
        int cnt = min(32, end - base);
        int id = (lane < cnt) ? g_edst[base + lane] : 0;
        int j = 0;
        for (; j + 2 <= cnt; j += 2) {
            int d0 = __shfl_sync(0xffffffffu, id, j);
            int d1 = __shfl_sync(0xffffffffu, id, j + 1);
            float w0 = g_isd[d0];
            float w1 = g_isd[d1];
            float2 v0 = *(const float2*)&g_h[(size_t)d0 * H_OUT + c];
            float2 v1 = *(const float2*)&g_h[(size_t)d1 * H_OUT + c];
            accx += w0 * v0.x;
            accy += w0 * v0.y;
            accx += w1 * v1.x;
            accy += w1 * v1.y;
        }
        if (j < cnt) {
            int d0 = __shfl_sync(0xffffffffu, id, j);
            float w0 = g_isd[d0];
            float2 v0 = *(const float2*)&g_h[(size_t)d0 * H_OUT + c];
            accx += w0 * v0.x;
            accy += w0 * v0.y;
        }
    }

    float dd   = (float)deg;
    float de   = (dd > 0.f) ? (dd * dd / fmaxf(dd, 1.f)) : 0.f;   // == deg (deg>=1)
    float isdi = g_isd[w];

    float s0 = gamma[c]     * rsqrtf(var[c]     + BN_EPS);
    float s1 = gamma[c + 1] * rsqrtf(var[c + 1] + BN_EPS);
    float t0 = beta[c]     - mean[c]     * s0;
    float t1 = beta[c + 1] - mean[c + 1] * s1;

    float2 hv = *(const float2*)&g_h[(size_t)w * H_OUT + c];
    float2 o;
    o.x = t0 + 0.5f * de * hv.x + 0.5f * isdi * accx;
    o.y = t1 + 0.5f * de * hv.y + 0.5f * isdi * accy;
    *(float2*)&out[(size_t)w * H_OUT + c] = o;
}

// ---------------- launch ----------------
extern "C" void kernel_launch(void* const* d_in, const int* in_sizes, int n_in,
                              void* d_out, int out_size) {
    const float* X     = (const float*)d_in[0];
    const float* W     = (const float*)d_in[1];
    const float* bias  = (const float*)d_in[2];
    const float* gamma = (const float*)d_in[3];
    const float* beta  = (const float*)d_in[4];
    const float* mean  = (const float*)d_in[5];
    const float* var   = (const float*)d_in[6];
    const int2*  ei    = (const int2*)d_in[7];
    float* out = (float*)d_out;

    zero_deg_kernel<<<(N_NODES + 255) / 256, 256>>>();
    count_deg_kernel<<<(N_EDGES + 255) / 256, 256>>>(ei);
    scanA_kernel<<<N_SCAN_BLOCKS, SCAN_THREADS>>>();
    scanB_kernel<<<1, 128>>>();
    scanC_kernel<<<N_SCAN_BLOCKS, SCAN_THREADS>>>();
    scatter_kernel<<<(N_EDGES + 255) / 256, 256>>>(ei);

    cudaFuncSetAttribute(gemm_kernel, cudaFuncAttributeMaxDynamicSharedMemorySize, GEMM_SMEM);
    gemm_kernel<<<(N_NODES + GEMM_NODES - 1) / GEMM_NODES, 256, GEMM_SMEM>>>(X, W, bias, gamma, var);

    gather_kernel<<<(N_NODES * 32 + 255) / 256, 256>>>(gamma, beta, mean, var, out);
}

// round 5
// speedup vs baseline: 1.4214x; 1.3451x over previous
#include <cuda_runtime.h>
#include <cuda_bf16.h>
#include <cstdint>

#define N_NODES 100000
#define N_EDGES 1000000
#define F_IN    128
#define H_OUT   64
#define BN_EPS  1e-3f

#define SCAN_NODES_PER_BLOCK 1024
#define SCAN_THREADS 256
#define N_SCAN_BLOCKS ((N_NODES + SCAN_NODES_PER_BLOCK - 1) / SCAN_NODES_PER_BLOCK)  // 98

// ---------------- device scratch ----------------
__device__ float g_h[(size_t)N_NODES * H_OUT];
__device__ int   g_deg[N_NODES];
__device__ float g_isd[N_NODES];
__device__ int   g_rowstart[N_NODES];
__device__ int   g_cursor[N_NODES];
__device__ int   g_edst[N_EDGES];
__device__ int   g_bsum[128];
__device__ int   g_boff[128];

__device__ __forceinline__ uint32_t smem_u32(const void* p) {
    uint32_t a;
    asm("{ .reg .u64 t; cvta.to.shared.u64 t, %1; cvt.u32.u64 %0, t; }" : "=r"(a) : "l"(p));
    return a;
}

// ---------------- prep kernels ----------------
__global__ void zero_deg_kernel() {
    int i = blockIdx.x * blockDim.x + threadIdx.x;
    if (i < N_NODES) g_deg[i] = 0;
}
__global__ void count_deg_kernel(const int2* __restrict__ ei) {
    int e = blockIdx.x * blockDim.x + threadIdx.x;
    if (e < N_EDGES) atomicAdd(&g_deg[ei[e].x], 1);
}
__global__ void scanA_kernel() {
    __shared__ int wsum[8];
    int b = blockIdx.x, t = threadIdx.x;
    int base = b * SCAN_NODES_PER_BLOCK + t * 4;
    int s = 0;
    #pragma unroll
    for (int j = 0; j < 4; j++)
        if (base + j < N_NODES) s += g_deg[base + j];
    #pragma unroll
    for (int o = 16; o > 0; o >>= 1) s += __shfl_down_sync(0xffffffffu, s, o);
    if ((t & 31) == 0) wsum[t >> 5] = s;
    __syncthreads();
    if (t == 0) {
        int tot = 0;
        #pragma unroll
        for (int w = 0; w < 8; w++) tot += wsum[w];
        g_bsum[b] = tot;
    }
}
__global__ void scanB_kernel() {
    __shared__ int sm[128];
    int t = threadIdx.x;
    int v = (t < N_SCAN_BLOCKS) ? g_bsum[t] : 0;
    sm[t] = v;
    __syncthreads();
    #pragma unroll
    for (int off = 1; off < 128; off <<= 1) {
        int u = (t >= off) ? sm[t - off] : 0;
        __syncthreads();
        sm[t] += u;
        __syncthreads();
    }
    if (t < N_SCAN_BLOCKS) g_boff[t] = sm[t] - v;
}
__global__ void scanC_kernel() {
    __shared__ int sm[SCAN_THREADS];
    int b = blockIdx.x, t = threadIdx.x;
    int base = b * SCAN_NODES_PER_BLOCK + t * 4;
    int d[4];
    int s = 0;
    #pragma unroll
    for (int j = 0; j < 4; j++) {
        d[j] = (base + j < N_NODES) ? g_deg[base + j] : 0;
        s += d[j];
    }
    sm[t] = s;
    __syncthreads();
    #pragma unroll
    for (int off = 1; off < SCAN_THREADS; off <<= 1) {
        int u = (t >= off) ? sm[t - off] : 0;
        __syncthreads();
        sm[t] += u;
        __syncthreads();
    }
    int row = g_boff[b] + (sm[t] - s);
    #pragma unroll
    for (int j = 0; j < 4; j++) {
        int i = base + j;
        if (i < N_NODES) {
            g_rowstart[i] = row;
            g_cursor[i]   = row;
            float dd = (float)d[j];
            g_isd[i] = (dd > 0.f) ? rsqrtf(dd) : 0.f;
            row += d[j];
        }
    }
}
__global__ void scatter_kernel(const int2* __restrict__ ei) {
    int e = blockIdx.x * blockDim.x + threadIdx.x;
    if (e < N_EDGES) {
        int2 p = __ldg(&ei[e]);
        int pos = atomicAdd(&g_cursor[p.x], 1);
        g_edst[pos] = p.y;
    }
}

// ---------------- tensor-core GEMM via mma.sync (bf16 3-split) ----------------
// g_h = (X @ W + b) * s, BN scale folded into W.
// Block: 256 threads (8 warps, 4x2), 128 nodes. A[128][128], B(=Ws^T)[64][128],
// bf16 hi/lo in smem, row pitch 272 B (conflict-free ldmatrix).
#define APITCH 272
#define SM_BS   0                      // 64 floats bias*s
#define SM_S    256                    // 64 floats s
#define SM_A_HI 1024
#define SM_A_LO (SM_A_HI + 128 * APITCH)   // +34816
#define SM_B_HI (SM_A_LO + 128 * APITCH)
#define SM_B_LO (SM_B_HI + 64 * APITCH)    // +17408
#define GEMM_SMEM (SM_B_LO + 64 * APITCH)  // 105472 B

__device__ __forceinline__ void ldmx4(uint32_t* r, uint32_t a) {
    asm volatile("ldmatrix.sync.aligned.m8n8.x4.shared.b16 {%0,%1,%2,%3}, [%4];"
                 : "=r"(r[0]), "=r"(r[1]), "=r"(r[2]), "=r"(r[3]) : "r"(a));
}
__device__ __forceinline__ void ldmx2(uint32_t* r, uint32_t a) {
    asm volatile("ldmatrix.sync.aligned.m8n8.x2.shared.b16 {%0,%1}, [%2];"
                 : "=r"(r[0]), "=r"(r[1]) : "r"(a));
}
__device__ __forceinline__ void mma_bf16(float* c, const uint32_t* a, const uint32_t* b) {
    asm volatile(
        "mma.sync.aligned.m16n8k16.row.col.f32.bf16.bf16.f32 "
        "{%0,%1,%2,%3}, {%4,%5,%6,%7}, {%8,%9}, {%0,%1,%2,%3};"
        : "+f"(c[0]), "+f"(c[1]), "+f"(c[2]), "+f"(c[3])
        : "r"(a[0]), "r"(a[1]), "r"(a[2]), "r"(a[3]), "r"(b[0]), "r"(b[1]));
}
__device__ __forceinline__ uint32_t pack_bf16(float x, float y) {
    __nv_bfloat16 bx = __float2bfloat16(x), by = __float2bfloat16(y);
    return ((uint32_t)*(uint16_t*)&by << 16) | *(uint16_t*)&bx;
}

__global__ void __launch_bounds__(256) gemm_mma_kernel(
    const float* __restrict__ X, const float* __restrict__ W,
    const float* __restrict__ bias,
    const float* __restrict__ gamma, const float* __restrict__ var)
{
    extern __shared__ char smem[];
    uint32_t sb = smem_u32(smem);
    int tid = threadIdx.x, wid = tid >> 5, lane = tid & 31;
    int node0 = blockIdx.x * 128;

    float* bs = (float*)(smem + SM_BS);
    float* sv = (float*)(smem + SM_S);
    if (tid < 64) {
        float s = gamma[tid] * rsqrtf(var[tid] + BN_EPS);
        sv[tid] = s;
        bs[tid] = bias[tid] * s;
    }
    __syncthreads();

    // Fill A: X tile [128 rows][128 cols] -> bf16 hi/lo, pitch 272
    {
        const float4* Xt = (const float4*)(X + (size_t)node0 * F_IN);
        #pragma unroll 4
        for (int i = tid; i < 4096; i += 256) {
            int r = i >> 5, c4 = i & 31;
            float4 v = make_float4(0.f, 0.f, 0.f, 0.f);
            if (node0 + r < N_NODES) v = Xt[i];
            float hx = __bfloat162float(__float2bfloat16(v.x));
            float hy = __bfloat162float(__float2bfloat16(v.y));
            float hz = __bfloat162float(__float2bfloat16(v.z));
            float hw = __bfloat162float(__float2bfloat16(v.w));
            uint2 hp, lp;
            hp.x = pack_bf16(v.x, v.y);
            hp.y = pack_bf16(v.z, v.w);
            lp.x = pack_bf16(v.x - hx, v.y - hy);
            lp.y = pack_bf16(v.z - hz, v.w - hw);
            uint32_t off = (uint32_t)(r * APITCH + c4 * 8);
            *(uint2*)(smem + SM_A_HI + off) = hp;
            *(uint2*)(smem + SM_A_LO + off) = lp;
        }
    }
    // Fill B: W[k][n] -> Ws[n][k] bf16 hi/lo (transpose, BN scale)
    #pragma unroll 4
    for (int i = tid; i < F_IN * H_OUT; i += 256) {
        int k = i >> 6, n = i & 63;
        float w = W[i] * sv[n];
        float hi = __bfloat162float(__float2bfloat16(w));
        uint32_t off = (uint32_t)(n * APITCH + k * 2);
        *(__nv_bfloat16*)(smem + SM_B_HI + off) = __float2bfloat16(w);
        *(__nv_bfloat16*)(smem + SM_B_LO + off) = __float2bfloat16(w - hi);
    }
    __syncthreads();

    int warp_m = wid & 3;    // 0..3 -> rows warp_m*32
    int warp_n = wid >> 2;   // 0..1 -> cols warp_n*32

    // ldmatrix base addresses (per-lane)
    uint32_t aAddr = sb + SM_A_HI
                   + (uint32_t)((warp_m * 32 + (lane & 15)) * APITCH)
                   + (uint32_t)((lane >> 4) * 16);
    uint32_t bAddr = sb + SM_B_HI
                   + (uint32_t)((warp_n * 32 + (lane & 7)) * APITCH)
                   + (uint32_t)(((lane >> 3) & 1) * 16);

    float c[2][4][4];
    #pragma unroll
    for (int mt = 0; mt < 2; mt++)
        #pragma unroll
        for (int nt = 0; nt < 4; nt++)
            #pragma unroll
            for (int q = 0; q < 4; q++) c[mt][nt][q] = 0.f;

    #pragma unroll
    for (int ks = 0; ks < 8; ks++) {
        uint32_t ko = (uint32_t)(ks * 32);
        uint32_t ah[2][4], al[2][4], bh[4][2], bl[4][2];
        #pragma unroll
        for (int mt = 0; mt < 2; mt++) {
            uint32_t a = aAddr + (uint32_t)(mt * 16 * APITCH) + ko;
            ldmx4(ah[mt], a);
            ldmx4(al[mt], a + (SM_A_LO - SM_A_HI));
        }
        #pragma unroll
        for (int nt = 0; nt < 4; nt++) {
            uint32_t b = bAddr + (uint32_t)(nt * 8 * APITCH) + ko;
            ldmx2(bh[nt], b);
            ldmx2(bl[nt], b + (SM_B_LO - SM_B_HI));
        }
        #pragma unroll
        for (int mt = 0; mt < 2; mt++)
            #pragma unroll
            for (int nt = 0; nt < 4; nt++) {
                mma_bf16(c[mt][nt], ah[mt], bh[nt]);   // hi*hi
                mma_bf16(c[mt][nt], ah[mt], bl[nt]);   // hi*lo
                mma_bf16(c[mt][nt], al[mt], bh[nt]);   // lo*hi
            }
    }

    // epilogue: c frag (m16n8): c0,c1 row=lane/4 cols 2*(lane%4); c2,c3 row+8
    int rbase = node0 + warp_m * 32 + (lane >> 2);
    int cgrp  = (lane & 3) * 2;
    #pragma unroll
    for (int nt = 0; nt < 4; nt++) {
        int col = warp_n * 32 + nt * 8 + cgrp;
        float2 bv = *(float2*)&bs[col];
        #pragma unroll
        for (int mt = 0; mt < 2; mt++) {
            int n1 = rbase + mt * 16;
            if (n1 < N_NODES) {
                float2 o = make_float2(c[mt][nt][0] + bv.x, c[mt][nt][1] + bv.y);
                *(float2*)&g_h[(size_t)n1 * H_OUT + col] = o;
            }
            int n2 = n1 + 8;
            if (n2 < N_NODES) {
                float2 o = make_float2(c[mt][nt][2] + bv.x, c[mt][nt][3] + bv.y);
                *(float2*)&g_h[(size_t)n2 * H_OUT + col] = o;
            }
        }
    }
}

// ---------------- fused gather: warp per node ----------------
__global__ __launch_bounds__(256) void gather_kernel(
    const float* __restrict__ gamma, const float* __restrict__ beta,
    const float* __restrict__ mean,  const float* __restrict__ var,
    float* __restrict__ out)
{
    int w    = (blockIdx.x * blockDim.x + threadIdx.x) >> 5;
    int lane = threadIdx.x & 31;
    if (w >= N_NODES) return;

    int start = g_rowstart[w];
    int deg   = g_deg[w];
    int end   = start + deg;
    int c     = lane * 2;

    float accx = 0.f, accy = 0.f;

    for (int base = start; base < end; base += 32) {
        int cnt = min(32, end - base);
        int id = (lane < cnt) ? g_edst[base + lane] : 0;
        int j = 0;
        for (; j + 2 <= cnt; j += 2) {
            int d0 = __shfl_sync(0xffffffffu, id, j);
            int d1 = __shfl_sync(0xffffffffu, id, j + 1);
            float w0 = g_isd[d0];
            float w1 = g_isd[d1];
            float2 v0 = *(const float2*)&g_h[(size_t)d0 * H_OUT + c];
            float2 v1 = *(const float2*)&g_h[(size_t)d1 * H_OUT + c];
            accx += w0 * v0.x;
            accy += w0 * v0.y;
            accx += w1 * v1.x;
            accy += w1 * v1.y;
        }
        if (j < cnt) {
            int d0 = __shfl_sync(0xffffffffu, id, j);
            float w0 = g_isd[d0];
            float2 v0 = *(const float2*)&g_h[(size_t)d0 * H_OUT + c];
            accx += w0 * v0.x;
            accy += w0 * v0.y;
        }
    }

    float dd   = (float)deg;
    float de   = (dd > 0.f) ? (dd * dd / fmaxf(dd, 1.f)) : 0.f;
    float isdi = g_isd[w];

    float s0 = gamma[c]     * rsqrtf(var[c]     + BN_EPS);
    float s1 = gamma[c + 1] * rsqrtf(var[c + 1] + BN_EPS);
    float t0 = beta[c]     - mean[c]     * s0;
    float t1 = beta[c + 1] - mean[c + 1] * s1;

    float2 hv = *(const float2*)&g_h[(size_t)w * H_OUT + c];
    float2 o;
    o.x = t0 + 0.5f * de * hv.x + 0.5f * isdi * accx;
    o.y = t1 + 0.5f * de * hv.y + 0.5f * isdi * accy;
    *(float2*)&out[(size_t)w * H_OUT + c] = o;
}

// ---------------- launch ----------------
extern "C" void kernel_launch(void* const* d_in, const int* in_sizes, int n_in,
                              void* d_out, int out_size) {
    const float* X     = (const float*)d_in[0];
    const float* W     = (const float*)d_in[1];
    const float* bias  = (const float*)d_in[2];
    const float* gamma = (const float*)d_in[3];
    const float* beta  = (const float*)d_in[4];
    const float* mean  = (const float*)d_in[5];
    const float* var   = (const float*)d_in[6];
    const int2*  ei    = (const int2*)d_in[7];
    float* out = (float*)d_out;

    zero_deg_kernel<<<(N_NODES + 255) / 256, 256>>>();
    count_deg_kernel<<<(N_EDGES + 255) / 256, 256>>>(ei);
    scanA_kernel<<<N_SCAN_BLOCKS, SCAN_THREADS>>>();
    scanB_kernel<<<1, 128>>>();
    scanC_kernel<<<N_SCAN_BLOCKS, SCAN_THREADS>>>();

    // 6th launch -> profiled by ncu (-s 5 -c 1)
    cudaFuncSetAttribute(gemm_mma_kernel, cudaFuncAttributeMaxDynamicSharedMemorySize, GEMM_SMEM);
    gemm_mma_kernel<<<(N_NODES + 127) / 128, 256, GEMM_SMEM>>>(X, W, bias, gamma, var);

    scatter_kernel<<<(N_EDGES + 255) / 256, 256>>>(ei);
    gather_kernel<<<(N_NODES * 32 + 255) / 256, 256>>>(gamma, beta, mean, var, out);
}

// round 6
// speedup vs baseline: 1.5656x; 1.1015x over previous
#include <cuda_runtime.h>
#include <cuda_bf16.h>
#include <cuda_fp16.h>
#include <cstdint>

#define N_NODES 100000
#define N_EDGES 1000000
#define F_IN    128
#define H_OUT   64
#define BN_EPS  1e-3f

// ---------------- device scratch ----------------
__device__ __half2 g_h2[(size_t)N_NODES * 32];   // isd-scaled, BN-scaled hidden feats (fp16)
__device__ int   g_deg[N_NODES];
__device__ float g_isd[N_NODES];
__device__ int   g_rowstart[N_NODES];
__device__ int   g_cursor[N_NODES];
__device__ int   g_edst[N_EDGES];
__device__ int   g_total;

__device__ __forceinline__ uint32_t smem_u32(const void* p) {
    uint32_t a;
    asm("{ .reg .u64 t; cvta.to.shared.u64 t, %1; cvt.u32.u64 %0, t; }" : "=r"(a) : "l"(p));
    return a;
}

// ---------------- prep kernels ----------------
__global__ void zero_deg_kernel() {
    int i = blockIdx.x * blockDim.x + threadIdx.x;
    if (i < N_NODES) g_deg[i] = 0;
    if (i == 0) g_total = 0;
}
__global__ void count_deg_kernel(const int2* __restrict__ ei) {
    int e = blockIdx.x * blockDim.x + threadIdx.x;
    if (e < N_EDGES) atomicAdd(&g_deg[ei[e].x], 1);
}
// fused scan: per-warp inclusive scan + one warp-aggregated atomic for the base.
// Bucket order across warps is arbitrary — gather only needs per-node ranges.
__global__ void scan_fused_kernel() {
    int i = blockIdx.x * blockDim.x + threadIdx.x;
    int lane = threadIdx.x & 31;
    int d = (i < N_NODES) ? g_deg[i] : 0;
    int p = d;
    #pragma unroll
    for (int o = 1; o < 32; o <<= 1) {
        int u = __shfl_up_sync(0xffffffffu, p, o);
        if (lane >= o) p += u;
    }
    int base = 0;
    if (lane == 31) base = atomicAdd(&g_total, p);   // p = warp total at lane 31
    base = __shfl_sync(0xffffffffu, base, 31);
    if (i < N_NODES) {
        int row = base + p - d;
        g_rowstart[i] = row;
        g_cursor[i]   = row;
        float dd = (float)d;
        g_isd[i] = (dd > 0.f) ? rsqrtf(dd) : 0.f;
    }
}
__global__ void scatter_kernel(const int2* __restrict__ ei) {
    int e = blockIdx.x * blockDim.x + threadIdx.x;
    if (e < N_EDGES) {
        int2 p = __ldg(&ei[e]);
        int pos = atomicAdd(&g_cursor[p.x], 1);
        g_edst[pos] = p.y;
    }
}

// ---------------- tensor-core GEMM via mma.sync (bf16 3-split) ----------------
// g_h2 = fp16( isd * ((X @ W)*s + b*s) ), BN scale s folded into W.
#define APITCH 272
#define SM_BS   0
#define SM_S    256
#define SM_A_HI 1024
#define SM_A_LO (SM_A_HI + 128 * APITCH)
#define SM_B_HI (SM_A_LO + 128 * APITCH)
#define SM_B_LO (SM_B_HI + 64 * APITCH)
#define GEMM_SMEM (SM_B_LO + 64 * APITCH)  // 105472 B

__device__ __forceinline__ void ldmx4(uint32_t* r, uint32_t a) {
    asm volatile("ldmatrix.sync.aligned.m8n8.x4.shared.b16 {%0,%1,%2,%3}, [%4];"
                 : "=r"(r[0]), "=r"(r[1]), "=r"(r[2]), "=r"(r[3]) : "r"(a));
}
__device__ __forceinline__ void ldmx2(uint32_t* r, uint32_t a) {
    asm volatile("ldmatrix.sync.aligned.m8n8.x2.shared.b16 {%0,%1}, [%2];"
                 : "=r"(r[0]), "=r"(r[1]) : "r"(a));
}
__device__ __forceinline__ void mma_bf16(float* c, const uint32_t* a, const uint32_t* b) {
    asm volatile(
        "mma.sync.aligned.m16n8k16.row.col.f32.bf16.bf16.f32 "
        "{%0,%1,%2,%3}, {%4,%5,%6,%7}, {%8,%9}, {%0,%1,%2,%3};"
        : "+f"(c[0]), "+f"(c[1]), "+f"(c[2]), "+f"(c[3])
        : "r"(a[0]), "r"(a[1]), "r"(a[2]), "r"(a[3]), "r"(b[0]), "r"(b[1]));
}
__device__ __forceinline__ uint32_t pack_bf16(float x, float y) {
    __nv_bfloat16 bx = __float2bfloat16(x), by = __float2bfloat16(y);
    return ((uint32_t)*(uint16_t*)&by << 16) | *(uint16_t*)&bx;
}

__global__ void __launch_bounds__(256) gemm_mma_kernel(
    const float* __restrict__ X, const float* __restrict__ W,
    const float* __restrict__ bias,
    const float* __restrict__ gamma, const float* __restrict__ var)
{
    extern __shared__ char smem[];
    uint32_t sb = smem_u32(smem);
    int tid = threadIdx.x, wid = tid >> 5, lane = tid & 31;
    int node0 = blockIdx.x * 128;

    float* bs = (float*)(smem + SM_BS);
    float* sv = (float*)(smem + SM_S);
    if (tid < 64) {
        float s = gamma[tid] * rsqrtf(var[tid] + BN_EPS);
        sv[tid] = s;
        bs[tid] = bias[tid] * s;
    }
    __syncthreads();

    // A: X tile [128][128] -> bf16 hi/lo
    {
        const float4* Xt = (const float4*)(X + (size_t)node0 * F_IN);
        #pragma unroll 4
        for (int i = tid; i < 4096; i += 256) {
            int r = i >> 5, c4 = i & 31;
            float4 v = make_float4(0.f, 0.f, 0.f, 0.f);
            if (node0 + r < N_NODES) v = Xt[i];
            float hx = __bfloat162float(__float2bfloat16(v.x));
            float hy = __bfloat162float(__float2bfloat16(v.y));
            float hz = __bfloat162float(__float2bfloat16(v.z));
            float hw = __bfloat162float(__float2bfloat16(v.w));
            uint2 hp, lp;
            hp.x = pack_bf16(v.x, v.y);
            hp.y = pack_bf16(v.z, v.w);
            lp.x = pack_bf16(v.x - hx, v.y - hy);
            lp.y = pack_bf16(v.z - hz, v.w - hw);
            uint32_t off = (uint32_t)(r * APITCH + c4 * 8);
            *(uint2*)(smem + SM_A_HI + off) = hp;
            *(uint2*)(smem + SM_A_LO + off) = lp;
        }
    }
    // B: W[k][n] -> Ws[n][k] bf16 hi/lo (transpose + BN scale)
    #pragma unroll 4
    for (int i = tid; i < F_IN * H_OUT; i += 256) {
        int k = i >> 6, n = i & 63;
        float w = W[i] * sv[n];
        float hi = __bfloat162float(__float2bfloat16(w));
        uint32_t off = (uint32_t)(n * APITCH + k * 2);
        *(__nv_bfloat16*)(smem + SM_B_HI + off) = __float2bfloat16(w);
        *(__nv_bfloat16*)(smem + SM_B_LO + off) = __float2bfloat16(w - hi);
    }
    __syncthreads();

    int warp_m = wid & 3;
    int warp_n = wid >> 2;

    uint32_t aAddr = sb + SM_A_HI
                   + (uint32_t)((warp_m * 32 + (lane & 15)) * APITCH)
                   + (uint32_t)((lane >> 4) * 16);
    uint32_t bAddr = sb + SM_B_HI
                   + (uint32_t)((warp_n * 32 + (lane & 7)) * APITCH)
                   + (uint32_t)(((lane >> 3) & 1) * 16);

    float c[2][4][4];
    #pragma unroll
    for (int mt = 0; mt < 2; mt++)
        #pragma unroll
        for (int nt = 0; nt < 4; nt++)
            #pragma unroll
            for (int q = 0; q < 4; q++) c[mt][nt][q] = 0.f;

    #pragma unroll
    for (int ks = 0; ks < 8; ks++) {
        uint32_t ko = (uint32_t)(ks * 32);
        uint32_t ah[2][4], al[2][4], bh[4][2], bl[4][2];
        #pragma unroll
        for (int mt = 0; mt < 2; mt++) {
            uint32_t a = aAddr + (uint32_t)(mt * 16 * APITCH) + ko;
            ldmx4(ah[mt], a);
            ldmx4(al[mt], a + (SM_A_LO - SM_A_HI));
        }
        #pragma unroll
        for (int nt = 0; nt < 4; nt++) {
            uint32_t b = bAddr + (uint32_t)(nt * 8 * APITCH) + ko;
            ldmx2(bh[nt], b);
            ldmx2(bl[nt], b + (SM_B_LO - SM_B_HI));
        }
        #pragma unroll
        for (int mt = 0; mt < 2; mt++)
            #pragma unroll
            for (int nt = 0; nt < 4; nt++) {
                mma_bf16(c[mt][nt], ah[mt], bh[nt]);
                mma_bf16(c[mt][nt], ah[mt], bl[nt]);
                mma_bf16(c[mt][nt], al[mt], bh[nt]);
            }
    }

    // epilogue: add bias*s, multiply by isd[row], store fp16 half2
    int rbase = node0 + warp_m * 32 + (lane >> 2);
    int cgrp  = (lane & 3) * 2;
    #pragma unroll
    for (int mt = 0; mt < 2; mt++) {
        int n1 = rbase + mt * 16;
        int n2 = n1 + 8;
        float i1 = (n1 < N_NODES) ? __ldg(&g_isd[n1]) : 0.f;
        float i2 = (n2 < N_NODES) ? __ldg(&g_isd[n2]) : 0.f;
        #pragma unroll
        for (int nt = 0; nt < 4; nt++) {
            int col = warp_n * 32 + nt * 8 + cgrp;
            float2 bv = *(float2*)&bs[col];
            if (n1 < N_NODES)
                g_h2[(size_t)n1 * 32 + (col >> 1)] =
                    __floats2half2_rn((c[mt][nt][0] + bv.x) * i1, (c[mt][nt][1] + bv.y) * i1);
            if (n2 < N_NODES)
                g_h2[(size_t)n2 * 32 + (col >> 1)] =
                    __floats2half2_rn((c[mt][nt][2] + bv.x) * i2, (c[mt][nt][3] + bv.y) * i2);
        }
    }
}

// ---------------- fused gather: warp per node, fp16 rows ----------------
// out[i] = t + 0.5*deg^1.5*h2[i] + 0.5*isd[i]*sum_d h2[d]
__global__ __launch_bounds__(256) void gather_kernel(
    const float* __restrict__ gamma, const float* __restrict__ beta,
    const float* __restrict__ mean,  const float* __restrict__ var,
    float* __restrict__ out)
{
    int w    = (blockIdx.x * blockDim.x + threadIdx.x) >> 5;
    int lane = threadIdx.x & 31;
    if (w >= N_NODES) return;

    int start = g_rowstart[w];
    int deg   = g_deg[w];
    int end   = start + deg;

    float accx = 0.f, accy = 0.f;

    for (int base = start; base < end; base += 32) {
        int cnt = min(32, end - base);
        int id = (lane < cnt) ? g_edst[base + lane] : 0;
        int j = 0;
        for (; j + 4 <= cnt; j += 4) {
            int d0 = __shfl_sync(0xffffffffu, id, j);
            int d1 = __shfl_sync(0xffffffffu, id, j + 1);
            int d2 = __shfl_sync(0xffffffffu, id, j + 2);
            int d3 = __shfl_sync(0xffffffffu, id, j + 3);
            float2 f0 = __half22float2(__ldg(&g_h2[(size_t)d0 * 32 + lane]));
            float2 f1 = __half22float2(__ldg(&g_h2[(size_t)d1 * 32 + lane]));
            float2 f2 = __half22float2(__ldg(&g_h2[(size_t)d2 * 32 + lane]));
            float2 f3 = __half22float2(__ldg(&g_h2[(size_t)d3 * 32 + lane]));
            accx += f0.x + f1.x + f2.x + f3.x;
            accy += f0.y + f1.y + f2.y + f3.y;
        }
        for (; j < cnt; j++) {
            int d0 = __shfl_sync(0xffffffffu, id, j);
            float2 f0 = __half22float2(__ldg(&g_h2[(size_t)d0 * 32 + lane]));
            accx += f0.x;
            accy += f0.y;
        }
    }

    float dd    = (float)deg;
    float isdi  = g_isd[w];
    float selfc = 0.5f * dd * sqrtf(dd);     // 0.5 * deg^1.5 (deg >= 1 always)

    int c = lane * 2;
    float s0 = gamma[c]     * rsqrtf(var[c]     + BN_EPS);
    float s1 = gamma[c + 1] * rsqrtf(var[c + 1] + BN_EPS);
    float t0 = beta[c]     - mean[c]     * s0;
    float t1 = beta[c + 1] - mean[c + 1] * s1;

    float2 hv = __half22float2(g_h2[(size_t)w * 32 + lane]);
    float2 o;
    o.x = t0 + selfc * hv.x + 0.5f * isdi * accx;
    o.y = t1 + selfc * hv.y + 0.5f * isdi * accy;
    *(float2*)&out[(size_t)w * H_OUT + c] = o;
}

// ---------------- launch ----------------
extern "C" void kernel_launch(void* const* d_in, const int* in_sizes, int n_in,
                              void* d_out, int out_size) {
    const float* X     = (const float*)d_in[0];
    const float* W     = (const float*)d_in[1];
    const float* bias  = (const float*)d_in[2];
    const float* gamma = (const float*)d_in[3];
    const float* beta  = (const float*)d_in[4];
    const float* mean  = (const float*)d_in[5];
    const float* var   = (const float*)d_in[6];
    const int2*  ei    = (const int2*)d_in[7];
    float* out = (float*)d_out;

    zero_deg_kernel<<<(N_NODES + 255) / 256, 256>>>();
    count_deg_kernel<<<(N_EDGES + 255) / 256, 256>>>(ei);
    scan_fused_kernel<<<(N_NODES + 255) / 256, 256>>>();
    scatter_kernel<<<(N_EDGES + 255) / 256, 256>>>(ei);

    cudaFuncSetAttribute(gemm_mma_kernel, cudaFuncAttributeMaxDynamicSharedMemorySize, GEMM_SMEM);
    gemm_mma_kernel<<<(N_NODES + 127) / 128, 256, GEMM_SMEM>>>(X, W, bias, gamma, var);

    gather_kernel<<<(N_NODES * 32 + 255) / 256, 256>>>(gamma, beta, mean, var, out);
}